// round 4
// baseline (speedup 1.0000x reference)
#include <cuda_runtime.h>
#include <cuda_bf16.h>

// Gumbel-Sinkhorn via u/v diagonal-scaling form, quarter-split matvecs.
// X0 = exp((sigmoid(gamma)+noise - rowmax)/T); 20x { u=1/(X0 v); v=1/(X0^T u) }; out = u_i X0_ij v_j.
// One block of 64 threads per matrix. Thread t (q=t/16, s=t%16) holds
//   rows {s,s+16,s+32,s+48} x cols [16q,16q+16)  (xr, packed f32x2)
//   cols {s,s+16,s+32,s+48} x rows [16q,16q+16)  (xc, packed f32x2)
// Per matvec: 4 broadcast LDS.128 (16 wf) instead of 16 (64 wf); partials
// combined via shfl.xor(16) + small smem exchange. Kills the L1 wavefront
// bottleneck (smem broadcast delivers bytes-per-lane; no dedup).

#define EX2F(d, x)       asm("ex2.approx.f32 %0, %1;" : "=f"(d) : "f"(x))
#define RCPF(d, x)       asm("rcp.approx.f32 %0, %1;" : "=f"(d) : "f"(x))
#define PACK2(d, lo, hi) asm("mov.b64 %0, {%1, %2};" : "=l"(d) : "f"(lo), "f"(hi))
#define UNPACK2(lo, hi, s) asm("mov.b64 {%0, %1}, %2;" : "=f"(lo), "=f"(hi) : "l"(s))
#define FMA2(acc, a, b)  asm("fma.rn.f32x2 %0, %1, %2, %0;" : "+l"(acc) : "l"(a), "l"(b))
#define ADD2(d, a, b)    asm("add.rn.f32x2 %0, %1, %2;" : "=l"(d) : "l"(a), "l"(b))
#define MUL2(d, a, b)    asm("mul.rn.f32x2 %0, %1, %2;" : "=l"(d) : "l"(a), "l"(b))

__device__ float g_sig[4096];  // sigmoid(gamma), computed once per launch

__global__ void sigmoid_kernel(const float* __restrict__ gamma) {
    int i = blockIdx.x * blockDim.x + threadIdx.x;
    if (i < 4096) {
        float x = gamma[i];
        float e; EX2F(e, -x * 1.4426950408889634f);
        float s; RCPF(s, 1.0f + e);
        g_sig[i] = s;
    }
}

// One half-update: dst = 1 ./ (X * src), X given as the quarter-split tile x[32].
// Thread (q,s): x[8k+j] = packed pair of X[rowset(s)[k]][16q+2j .. +2j+1] (or the
// transposed equivalent). Exchange: shfl.xor(16) within warp, smem across warps.
__device__ __forceinline__ void half_update(const unsigned long long (&x)[32],
                                            const float* __restrict__ src,
                                            float* __restrict__ dst,
                                            unsigned long long (&pE)[2][4][17],
                                            int q, int s, int lane, int w, int t) {
    const ulonglong2* S2 = reinterpret_cast<const ulonglong2*>(src) + 4 * q;
    ulonglong2 c0 = S2[0], c1 = S2[1], c2 = S2[2], c3 = S2[3];
    unsigned long long pr[4];
#pragma unroll
    for (int k = 0; k < 4; k++) {
        unsigned long long a0 = 0ull, a1 = 0ull;
        FMA2(a0, x[8 * k + 0], c0.x); FMA2(a1, x[8 * k + 1], c0.y);
        FMA2(a0, x[8 * k + 2], c1.x); FMA2(a1, x[8 * k + 3], c1.y);
        FMA2(a0, x[8 * k + 4], c2.x); FMA2(a1, x[8 * k + 5], c2.y);
        FMA2(a0, x[8 * k + 6], c3.x); FMA2(a1, x[8 * k + 7], c3.y);
        ADD2(pr[k], a0, a1);
        unsigned long long o = __shfl_xor_sync(0xffffffffu, pr[k], 16);
        ADD2(pr[k], pr[k], o);
    }
    if (!(lane & 16)) {
#pragma unroll
        for (int k = 0; k < 4; k++) pE[w][k][s] = pr[k];
    }
    __syncthreads();
    // owner: thread t finalizes element t (= (t&15) + 16*(t>>4))
    int rs = t & 15, rk = t >> 4;
    unsigned long long h0 = pE[0][rk][rs], h1 = pE[1][rk][rs];
    unsigned long long hs; ADD2(hs, h0, h1);
    float lo, hi; UNPACK2(lo, hi, hs);
    float y = lo + hi;
    float r; RCPF(r, y);
    dst[t] = r;
    __syncthreads();
}

__global__ void __launch_bounds__(64) sinkhorn_kernel(const float* __restrict__ noise,
                                                      float* __restrict__ out) {
    __shared__ __align__(16) float sA[64 * 68];  // stride 68: float4-aligned rows
    __shared__ __align__(16) float sU[64];
    __shared__ __align__(16) float sV[64];
    __shared__ __align__(16) unsigned long long pE[2][4][17];  // [warp][k][s], padded

    const int b = blockIdx.x;
    const int t = threadIdx.x;   // 0..63
    const int w = t >> 5;        // warp
    const int lane = t & 31;
    const int q = t >> 4;        // 0..3 column-quarter
    const int s = t & 15;        // 0..15

    // ---- phase A: coalesced load noise + sigmoid(gamma) into smem ----
    const float4* __restrict__ n4 = reinterpret_cast<const float4*>(noise) + (size_t)b * 1024;
    const float4* __restrict__ g4 = reinterpret_cast<const float4*>(g_sig);
#pragma unroll
    for (int k = 0; k < 16; k++) {
        int idx = k * 64 + t;
        float4 nv = n4[idx];
        float4 gv = g4[idx];
        float4 av = make_float4(nv.x + gv.x, nv.y + gv.y, nv.z + gv.z, nv.w + gv.w);
        int row = idx >> 4, c4 = idx & 15;
        *reinterpret_cast<float4*>(sA + row * 68 + c4 * 4) = av;
    }
    __syncthreads();

    // ---- phase B: thread t exponentiates row t, u0 = 1/rowsum ----
    {
        float a[64];
#pragma unroll
        for (int k = 0; k < 16; k++) {
            float4 v = *reinterpret_cast<const float4*>(sA + t * 68 + k * 4);
            a[4 * k + 0] = v.x; a[4 * k + 1] = v.y; a[4 * k + 2] = v.z; a[4 * k + 3] = v.w;
        }
        float mx[8];
#pragma unroll
        for (int k = 0; k < 8; k++) {
            float mm = a[8 * k];
#pragma unroll
            for (int j = 1; j < 8; j++) mm = fmaxf(mm, a[8 * k + j]);
            mx[k] = mm;
        }
        float m = fmaxf(fmaxf(fmaxf(mx[0], mx[1]), fmaxf(mx[2], mx[3])),
                        fmaxf(fmaxf(mx[4], mx[5]), fmaxf(mx[6], mx[7])));
        const float C = 14.426950408889634f;  // log2(e)/0.1
        float rs0 = 0.f, rs1 = 0.f;
#pragma unroll
        for (int j = 0; j < 32; j++) {
            float e0, e1;
            EX2F(e0, (a[2 * j + 0] - m) * C);
            EX2F(e1, (a[2 * j + 1] - m) * C);
            rs0 += e0; rs1 += e1;
            *reinterpret_cast<float2*>(sA + t * 68 + 2 * j) = make_float2(e0, e1);
        }
        float u0; RCPF(u0, rs0 + rs1);
        sU[t] = u0;
    }
    __syncthreads();

    // ---- phase C: build quarter-split register tiles ----
    unsigned long long xr[32];  // rows {s+16k} x cols [16q,16q+16)
    unsigned long long xc[32];  // cols {s+16k} x rows [16q,16q+16)
#pragma unroll
    for (int k = 0; k < 4; k++) {
        int row = s + 16 * k;
        const ulonglong2* src = reinterpret_cast<const ulonglong2*>(sA + row * 68 + 16 * q);
        ulonglong2 e0 = src[0], e1 = src[1], e2 = src[2], e3 = src[3];
        xr[8 * k + 0] = e0.x; xr[8 * k + 1] = e0.y;
        xr[8 * k + 2] = e1.x; xr[8 * k + 3] = e1.y;
        xr[8 * k + 4] = e2.x; xr[8 * k + 5] = e2.y;
        xr[8 * k + 6] = e3.x; xr[8 * k + 7] = e3.y;
    }
#pragma unroll
    for (int k = 0; k < 4; k++) {
        int c = s + 16 * k;
#pragma unroll
        for (int j = 0; j < 8; j++) {
            float f0 = sA[(16 * q + 2 * j + 0) * 68 + c];
            float f1 = sA[(16 * q + 2 * j + 1) * 68 + c];
            PACK2(xc[8 * k + j], f0, f1);
        }
    }

    // ---- 20 Sinkhorn iterations (u0 done): 19x (v,u) + final v ----
#pragma unroll 1
    for (int it = 0; it < 19; ++it) {
        half_update(xc, sU, sV, pE, q, s, lane, w, t);  // v = 1/(X0^T u)
        half_update(xr, sV, sU, pE, q, s, lane, w, t);  // u = 1/(X0 v)
    }
    half_update(xc, sU, sV, pE, q, s, lane, w, t);      // final v (20th col-normalize)

    // ---- epilogue: out[r][j] = u_r * X0[r][j] * v_j ----
    {
        float uks[4] = {sU[s], sU[s + 16], sU[s + 32], sU[s + 48]};
        const ulonglong2* V2 = reinterpret_cast<const ulonglong2*>(sV) + 4 * q;
        ulonglong2 d0 = V2[0], d1 = V2[1], d2 = V2[2], d3 = V2[3];
        unsigned long long wv[8] = {d0.x, d0.y, d1.x, d1.y, d2.x, d2.y, d3.x, d3.y};
#pragma unroll
        for (int k = 0; k < 4; k++) {
            unsigned long long u2; PACK2(u2, uks[k], uks[k]);
            int row = s + 16 * k;
            float4* o4 = reinterpret_cast<float4*>(out + (size_t)b * 4096 + row * 64 + 16 * q);
#pragma unroll
            for (int j = 0; j < 4; j++) {
                unsigned long long p0, p1;
                MUL2(p0, xr[8 * k + 2 * j + 0], wv[2 * j + 0]); MUL2(p0, p0, u2);
                MUL2(p1, xr[8 * k + 2 * j + 1], wv[2 * j + 1]); MUL2(p1, p1, u2);
                float4 o;
                UNPACK2(o.x, o.y, p0);
                UNPACK2(o.z, o.w, p1);
                o4[j] = o;
            }
        }
    }
}

extern "C" void kernel_launch(void* const* d_in, const int* in_sizes, int n_in,
                              void* d_out, int out_size) {
    const float* gamma = (const float*)d_in[0];
    const float* noise = (const float*)d_in[1];
    int s0 = in_sizes[0], s1 = (n_in >= 2) ? in_sizes[1] : 0;
    if (s0 > s1) {  // defensive: gamma is the small one (4096 elements)
        const float* tmp = gamma; gamma = noise; noise = tmp;
        int ts = s0; s0 = s1; s1 = ts;
    }
    int num_matrices = s1 / 4096;  // 8192 for the reference shapes
    float* out = (float*)d_out;

    sigmoid_kernel<<<16, 256>>>(gamma);
    sinkhorn_kernel<<<num_matrices, 64>>>(noise, out);
}

// round 11
// speedup vs baseline: 1.0050x; 1.0050x over previous
#include <cuda_runtime.h>
#include <cuda_bf16.h>

// Gumbel-Sinkhorn, u/v diagonal-scaling form, ONE MATRIX PER WARP.
// X0 = exp((sigmoid(gamma)+noise - rowmax)/T); 20x {u=1/(X0 v); v=1/(X0^T u)};
// out = u_i X0_ij v_j.
// Lane l=(q=l>>3, s=l&7) holds tile T[k][j] = packed (X0[s+8k][16q+2j], [..+2j+1]),
// k,j in 0..7 (64 packed regs). Both matvecs are in-warp shfl butterflies with
// data halving; no shared memory, no __syncthreads -> no barrier latency.
// Ownership maps: after row-reduce lane owns rows (s+16*perm[q], +8), perm={0,2,1,3}
// (involution). After col-reduce lane owns cols (16q+2*mt[s], +1), mt = bit-reverse
// {0,4,2,6,1,5,3,7} (involution).

#define EX2F(d, x)       asm("ex2.approx.f32 %0, %1;" : "=f"(d) : "f"(x))
#define RCPF(d, x)       asm("rcp.approx.f32 %0, %1;" : "=f"(d) : "f"(x))
#define PACK2(d, lo, hi) asm("mov.b64 %0, {%1, %2};" : "=l"(d) : "f"(lo), "f"(hi))
#define UNPACK2(lo, hi, s) asm("mov.b64 {%0, %1}, %2;" : "=f"(lo), "=f"(hi) : "l"(s))
#define FMA2(acc, a, b)  asm("fma.rn.f32x2 %0, %1, %2, %0;" : "+l"(acc) : "l"(a), "l"(b))
#define ADD2(d, a, b)    asm("add.rn.f32x2 %0, %1, %2;" : "=l"(d) : "l"(a), "l"(b))
#define MUL2(d, a, b)    asm("mul.rn.f32x2 %0, %1, %2;" : "=l"(d) : "l"(a), "l"(b))

__device__ float g_sig[4096];  // sigmoid(gamma)

__global__ void sigmoid_kernel(const float* __restrict__ gamma) {
    int i = blockIdx.x * blockDim.x + threadIdx.x;
    if (i < 4096) {
        float x = gamma[i];
        float e; EX2F(e, -x * 1.4426950408889634f);
        float s; RCPF(s, 1.0f + e);
        g_sig[i] = s;
    }
}

__device__ __forceinline__ unsigned long long rcp2(unsigned long long y) {
    float lo, hi; UNPACK2(lo, hi, y);
    float a, b; RCPF(a, lo); RCPF(b, hi);
    unsigned long long r; PACK2(r, a, b);
    return r;
}

// Reduce 8 per-row scalars over the 4 q-lanes (xor 8, xor 16) with halving.
// Returns packed pair owned by this lane: rows (s + 16*perm[q], +8).
__device__ __forceinline__ unsigned long long row_reduce(const float (&pr)[8],
                                                         int qb0, int qb1) {
    unsigned long long P0, P1, P2, P3;
    PACK2(P0, pr[0], pr[1]); PACK2(P1, pr[2], pr[3]);
    PACK2(P2, pr[4], pr[5]); PACK2(P3, pr[6], pr[7]);
    unsigned long long s0 = qb0 ? P0 : P2;
    unsigned long long k0 = qb0 ? P2 : P0;
    unsigned long long s1 = qb0 ? P1 : P3;
    unsigned long long k1 = qb0 ? P3 : P1;
    unsigned long long r0 = __shfl_xor_sync(0xffffffffu, s0, 8);
    unsigned long long r1 = __shfl_xor_sync(0xffffffffu, s1, 8);
    unsigned long long Q0, Q1;
    ADD2(Q0, k0, r0);
    ADD2(Q1, k1, r1);
    unsigned long long s2 = qb1 ? Q0 : Q1;
    unsigned long long k2 = qb1 ? Q1 : Q0;
    unsigned long long r2 = __shfl_xor_sync(0xffffffffu, s2, 16);
    unsigned long long y; ADD2(y, k2, r2);
    return y;
}

__global__ void __launch_bounds__(128) sinkhorn_kernel(const float* __restrict__ noise,
                                                       float* __restrict__ out,
                                                       int num_matrices) {
    const int wid = threadIdx.x >> 5;
    const int lane = threadIdx.x & 31;
    const int b = blockIdx.x * 4 + wid;
    if (b >= num_matrices) return;           // whole-warp exit; no barriers anywhere
    const int q = lane >> 3;                  // 0..3 col-quarter
    const int s = lane & 7;                   // 0..7
    const int qb0 = q & 1, qb1 = q & 2;

    const float* __restrict__ A = noise + (size_t)b * 4096 + (s * 64 + q * 16);
    const float* __restrict__ G = g_sig + (s * 64 + q * 16);
    float* __restrict__ O = out + (size_t)b * 4096 + (s * 64 + q * 16);

    const float C = 14.426950408889634f;      // log2(e)/0.1

    unsigned long long T[8][8];               // the tile, packed col-pairs
    float pr[8];                              // per-row scalars (sums / partials)

    // ---- build tile: load, add gamma, per-row max (cross-lane), exp, row sums ----
#pragma unroll
    for (int k = 0; k < 8; k++) {
        float4 av[4];
#pragma unroll
        for (int j2 = 0; j2 < 4; j2++) {
            float4 n = *reinterpret_cast<const float4*>(A + k * 512 + j2 * 4);
            float4 g = *reinterpret_cast<const float4*>(G + k * 512 + j2 * 4);
            av[j2] = make_float4(n.x + g.x, n.y + g.y, n.z + g.z, n.w + g.w);
        }
        float m01 = fmaxf(fmaxf(av[0].x, av[0].y), fmaxf(av[0].z, av[0].w));
        float m23 = fmaxf(fmaxf(av[1].x, av[1].y), fmaxf(av[1].z, av[1].w));
        float m45 = fmaxf(fmaxf(av[2].x, av[2].y), fmaxf(av[2].z, av[2].w));
        float m67 = fmaxf(fmaxf(av[3].x, av[3].y), fmaxf(av[3].z, av[3].w));
        float m = fmaxf(fmaxf(m01, m23), fmaxf(m45, m67));
        m = fmaxf(m, __shfl_xor_sync(0xffffffffu, m, 8));
        m = fmaxf(m, __shfl_xor_sync(0xffffffffu, m, 16));
        float mc = m * C;
        unsigned long long rs = 0ull;
#pragma unroll
        for (int j2 = 0; j2 < 4; j2++) {
            float e0, e1, e2, e3;
            EX2F(e0, fmaf(av[j2].x, C, -mc));
            EX2F(e1, fmaf(av[j2].y, C, -mc));
            EX2F(e2, fmaf(av[j2].z, C, -mc));
            EX2F(e3, fmaf(av[j2].w, C, -mc));
            unsigned long long t0, t1;
            PACK2(t0, e0, e1); PACK2(t1, e2, e3);
            T[k][2 * j2] = t0; T[k][2 * j2 + 1] = t1;
            ADD2(rs, rs, t0); ADD2(rs, rs, t1);
        }
        float lo, hi; UNPACK2(lo, hi, rs);
        pr[k] = lo + hi;
    }

    // u0 = 1/(X0 * ones): lane owns rows (s+16*perm[q], +8)
    unsigned long long uP = rcp2(row_reduce(pr, qb0, qb1));
    unsigned long long vP = 0ull;
    unsigned long long uB[8];                 // broadcast-duplicated u per row k
    unsigned long long vq[8];                 // v packed pairs for my 16 cols

    const int sb0 = s & 1, sb1 = s & 2, sb2 = s & 4;

#pragma unroll 1
    for (int it = 0; it < 20; ++it) {
        // ---- col update: v = 1/(X0^T u) ----
        // gather uB: owner of rows (s+16j, s+16j+8) is lane (invperm[j], s), invperm={0,2,1,3}
        {
            unsigned long long g0 = __shfl_sync(0xffffffffu, uP, (0 << 3) + s);
            unsigned long long g1 = __shfl_sync(0xffffffffu, uP, (2 << 3) + s);
            unsigned long long g2 = __shfl_sync(0xffffffffu, uP, (1 << 3) + s);
            unsigned long long g3 = __shfl_sync(0xffffffffu, uP, (3 << 3) + s);
            float lo, hi;
            UNPACK2(lo, hi, g0); PACK2(uB[0], lo, lo); PACK2(uB[1], hi, hi);
            UNPACK2(lo, hi, g1); PACK2(uB[2], lo, lo); PACK2(uB[3], hi, hi);
            UNPACK2(lo, hi, g2); PACK2(uB[4], lo, lo); PACK2(uB[5], hi, hi);
            UNPACK2(lo, hi, g3); PACK2(uB[6], lo, lo); PACK2(uB[7], hi, hi);
        }
        unsigned long long acc[8];
#pragma unroll
        for (int j = 0; j < 8; j++) acc[j] = 0ull;
#pragma unroll
        for (int k = 0; k < 8; k++)
#pragma unroll
            for (int j = 0; j < 8; j++) FMA2(acc[j], T[k][j], uB[k]);
        // reduce over s-lanes with halving: xor 1, 2, 4
        unsigned long long B[4];
#pragma unroll
        for (int m = 0; m < 4; m++) {
            unsigned long long snd = sb0 ? acc[m] : acc[m + 4];
            unsigned long long kp  = sb0 ? acc[m + 4] : acc[m];
            unsigned long long r = __shfl_xor_sync(0xffffffffu, snd, 1);
            ADD2(B[m], kp, r);
        }
        unsigned long long Cc[2];
#pragma unroll
        for (int m = 0; m < 2; m++) {
            unsigned long long snd = sb1 ? B[m] : B[m + 2];
            unsigned long long kp  = sb1 ? B[m + 2] : B[m];
            unsigned long long r = __shfl_xor_sync(0xffffffffu, snd, 2);
            ADD2(Cc[m], kp, r);
        }
        {
            unsigned long long snd = sb2 ? Cc[0] : Cc[1];
            unsigned long long kp  = sb2 ? Cc[1] : Cc[0];
            unsigned long long r = __shfl_xor_sync(0xffffffffu, snd, 4);
            unsigned long long z; ADD2(z, kp, r);
            vP = rcp2(z);                     // lane owns cols (16q + 2*mt[s], +1)
        }
        if (it == 19) break;                  // 20th col-normalize is the last op

        // ---- row update: u = 1/(X0 v) ----
        // gather vq[j]: owner of cols (16q+2j,+1) is lane (q, mt[j]); mt bit-reverse
        vq[0] = __shfl_sync(0xffffffffu, vP, (q << 3) + 0);
        vq[1] = __shfl_sync(0xffffffffu, vP, (q << 3) + 4);
        vq[2] = __shfl_sync(0xffffffffu, vP, (q << 3) + 2);
        vq[3] = __shfl_sync(0xffffffffu, vP, (q << 3) + 6);
        vq[4] = __shfl_sync(0xffffffffu, vP, (q << 3) + 1);
        vq[5] = __shfl_sync(0xffffffffu, vP, (q << 3) + 5);
        vq[6] = __shfl_sync(0xffffffffu, vP, (q << 3) + 3);
        vq[7] = __shfl_sync(0xffffffffu, vP, (q << 3) + 7);
        unsigned long long accR[8];
#pragma unroll
        for (int k = 0; k < 8; k++) accR[k] = 0ull;
#pragma unroll
        for (int k = 0; k < 8; k++)
#pragma unroll
            for (int j = 0; j < 8; j++) FMA2(accR[k], T[k][j], vq[j]);
#pragma unroll
        for (int k = 0; k < 8; k++) {
            float lo, hi; UNPACK2(lo, hi, accR[k]);
            pr[k] = lo + hi;
        }
        uP = rcp2(row_reduce(pr, qb0, qb1));
    }

    // ---- epilogue: out[r][c] = u_r * X0[r][c] * v_c ----
    // uB still holds the final u broadcast pairs (from the last col update).
    vq[0] = __shfl_sync(0xffffffffu, vP, (q << 3) + 0);
    vq[1] = __shfl_sync(0xffffffffu, vP, (q << 3) + 4);
    vq[2] = __shfl_sync(0xffffffffu, vP, (q << 3) + 2);
    vq[3] = __shfl_sync(0xffffffffu, vP, (q << 3) + 6);
    vq[4] = __shfl_sync(0xffffffffu, vP, (q << 3) + 1);
    vq[5] = __shfl_sync(0xffffffffu, vP, (q << 3) + 5);
    vq[6] = __shfl_sync(0xffffffffu, vP, (q << 3) + 3);
    vq[7] = __shfl_sync(0xffffffffu, vP, (q << 3) + 7);
#pragma unroll
    for (int k = 0; k < 8; k++) {
#pragma unroll
        for (int j2 = 0; j2 < 4; j2++) {
            unsigned long long p0, p1;
            MUL2(p0, T[k][2 * j2 + 0], uB[k]); MUL2(p0, p0, vq[2 * j2 + 0]);
            MUL2(p1, T[k][2 * j2 + 1], uB[k]); MUL2(p1, p1, vq[2 * j2 + 1]);
            float4 o;
            UNPACK2(o.x, o.y, p0);
            UNPACK2(o.z, o.w, p1);
            *reinterpret_cast<float4*>(O + k * 512 + j2 * 4) = o;
        }
    }
}

extern "C" void kernel_launch(void* const* d_in, const int* in_sizes, int n_in,
                              void* d_out, int out_size) {
    const float* gamma = (const float*)d_in[0];
    const float* noise = (const float*)d_in[1];
    int s0 = in_sizes[0], s1 = (n_in >= 2) ? in_sizes[1] : 0;
    if (s0 > s1) {  // defensive: gamma is the small one (4096 elements)
        const float* tmp = gamma; gamma = noise; noise = tmp;
        int ts = s0; s0 = s1; s1 = ts;
    }
    int num_matrices = s1 / 4096;  // 8192 for the reference shapes
    float* out = (float*)d_out;

    sigmoid_kernel<<<16, 256>>>(gamma);
    sinkhorn_kernel<<<(num_matrices + 3) / 4, 128>>>(noise, out, num_matrices);
}